// round 1
// baseline (speedup 1.0000x reference)
#include <cuda_runtime.h>
#include <math_constants.h>

#define NROWS 65536
#define DDIM  256
#define KCB   1024
#define NCB   3

#define BM 64
#define BN 128
#define BK 32
#define NTHREADS 256

// ---------------- scratch (no allocations allowed) ----------------
__device__ float  g_res[(size_t)NROWS * DDIM];   // residual between stages (64 MB)
__device__ float  g_c2[NCB * KCB];               // per-stage ||c_k||^2
__device__ double g_loss[NCB];                   // per-stage sum of (code - r)^2

// ---------------- smem layout (floats) ----------------
// zT   : [256][68]  transposed z tile (stride 68 keeps float4 alignment)
// cbs  : [32][132]  codebook sub-tile, d-major (stride 132 to spread banks)
// c2sh : [1024]
// l2s  : [64]
// redS : [64*16]  per-thread best score
// redI : [64*16]  per-thread best index
// bidx : [64]
#define ZT_STRIDE 68
#define CB_STRIDE 132
#define OFF_ZT    0
#define OFF_CBS   (OFF_ZT   + 256 * ZT_STRIDE)        // 17408
#define OFF_C2    (OFF_CBS  + 32 * CB_STRIDE)         // 21632
#define OFF_L2    (OFF_C2   + 1024)                   // 22656
#define OFF_REDS  (OFF_L2   + 64)                     // 22720
#define OFF_REDI  (OFF_REDS + 64 * 16)                // 23744
#define OFF_BIDX  (OFF_REDI + 64 * 16)                // 24768
#define SMEM_FLOATS (OFF_BIDX + 64)                   // 24832
#define SMEM_BYTES  (SMEM_FLOATS * 4)                 // 99328

// ---------------- init: zero loss accumulators, compute c2 ----------------
__global__ void rvq_init_kernel(const float* __restrict__ cb,
                                float* __restrict__ c2out,
                                double* __restrict__ loss)
{
    if (blockIdx.x == 0 && threadIdx.x < NCB) loss[threadIdx.x] = 0.0;

    int gw   = (blockIdx.x * blockDim.x + threadIdx.x) >> 5;  // one warp per codeword
    int lane = threadIdx.x & 31;
    if (gw < NCB * KCB) {
        const float* row = cb + (size_t)gw * DDIM;
        float s = 0.f;
        for (int d = lane; d < DDIM; d += 32) { float v = row[d]; s = fmaf(v, v, s); }
        #pragma unroll
        for (int o = 16; o; o >>= 1) s += __shfl_xor_sync(0xffffffffu, s, o);
        if (lane == 0) c2out[gw] = s;
    }
}

// ---------------- fused stage: GEMM + argmin + gather/update/loss ----------------
__global__ __launch_bounds__(NTHREADS, 2)
void rvq_stage_kernel(const float* __restrict__ zin,   // residual input [N,D]
                      const float* __restrict__ cbg,   // codebook (stage offset applied) [K,D]
                      const float* __restrict__ c2g,   // stage c2 [K]
                      float* __restrict__ fq,          // output quantized [N,D]
                      float* __restrict__ rout,        // residual output [N,D]
                      double* __restrict__ lossp,      // stage loss accumulator
                      int firstStage, int writeR)
{
    extern __shared__ float sm[];
    float* zT   = sm + OFF_ZT;
    float* cbs  = sm + OFF_CBS;
    float* c2sh = sm + OFF_C2;
    float* l2s  = sm + OFF_L2;
    float* redS = sm + OFF_REDS;
    int*   redI = (int*)(sm + OFF_REDI);
    int*   bidx = (int*)(sm + OFF_BIDX);

    const int tid = threadIdx.x;
    const int m0  = blockIdx.x * BM;
    const int tx  = tid & 15;   // 0..15 -> k columns tx + 16*j
    const int ty  = tid >> 4;   // 0..15 -> rows 4*ty..4*ty+3

    // ---- load z tile transposed into smem (coalesced float4 reads) ----
    #pragma unroll
    for (int it = 0; it < 16; ++it) {
        int f  = tid + it * NTHREADS;          // 0..4095
        int m  = f >> 6;                       // row 0..63
        int d4 = f & 63;                       // float4 index along D
        float4 v = *(const float4*)(zin + (size_t)(m0 + m) * DDIM + d4 * 4);
        zT[(d4 * 4 + 0) * ZT_STRIDE + m] = v.x;
        zT[(d4 * 4 + 1) * ZT_STRIDE + m] = v.y;
        zT[(d4 * 4 + 2) * ZT_STRIDE + m] = v.z;
        zT[(d4 * 4 + 3) * ZT_STRIDE + m] = v.w;
    }
    // ---- stage c2 into smem ----
    #pragma unroll
    for (int i = tid; i < KCB; i += NTHREADS) c2sh[i] = c2g[i];
    __syncthreads();

    // ---- l2 per row ----
    if (tid < BM) {
        float s = 0.f;
        for (int d = 0; d < DDIM; ++d) { float v = zT[d * ZT_STRIDE + tid]; s = fmaf(v, v, s); }
        l2s[tid] = s;
    }
    __syncthreads();

    // ---- GEMM + argmin over K in tiles of BN ----
    float best[4];
    int   bi[4];
    #pragma unroll
    for (int r = 0; r < 4; ++r) { best[r] = CUDART_INF_F; bi[r] = 0; }

    for (int kt = 0; kt < KCB / BN; ++kt) {
        float acc[4][8];
        #pragma unroll
        for (int r = 0; r < 4; ++r)
            #pragma unroll
            for (int j = 0; j < 8; ++j) acc[r][j] = 0.f;

        for (int dt = 0; dt < DDIM / BK; ++dt) {
            // load cb sub-tile [BN k][BK d] transposed into cbs[d][k]
            {
                int kl = tid >> 3;            // 0..31
                int dl = (tid & 7) << 2;      // 0,4,...,28
                #pragma unroll
                for (int kk = 0; kk < 4; ++kk) {
                    int k = kl + kk * 32;
                    float4 v = *(const float4*)(cbg + (size_t)(kt * BN + k) * DDIM + dt * BK + dl);
                    cbs[(dl + 0) * CB_STRIDE + k] = v.x;
                    cbs[(dl + 1) * CB_STRIDE + k] = v.y;
                    cbs[(dl + 2) * CB_STRIDE + k] = v.z;
                    cbs[(dl + 3) * CB_STRIDE + k] = v.w;
                }
            }
            __syncthreads();

            #pragma unroll
            for (int d = 0; d < BK; ++d) {
                float4 zv = *(const float4*)&zT[(dt * BK + d) * ZT_STRIDE + ty * 4];
                float cf[8];
                #pragma unroll
                for (int j = 0; j < 8; ++j) cf[j] = cbs[d * CB_STRIDE + tx + j * 16];
                #pragma unroll
                for (int j = 0; j < 8; ++j) {
                    acc[0][j] = fmaf(zv.x, cf[j], acc[0][j]);
                    acc[1][j] = fmaf(zv.y, cf[j], acc[1][j]);
                    acc[2][j] = fmaf(zv.z, cf[j], acc[2][j]);
                    acc[3][j] = fmaf(zv.w, cf[j], acc[3][j]);
                }
            }
            __syncthreads();
        }

        // fold distances (replicating reference rounding: (l2 - 2*cl) + c2)
        #pragma unroll
        for (int r = 0; r < 4; ++r) {
            float l2v = l2s[ty * 4 + r];
            #pragma unroll
            for (int j = 0; j < 8; ++j) {
                int kg = kt * BN + tx + j * 16;           // ascending within thread
                float s = (l2v - 2.0f * acc[r][j]) + c2sh[kg];
                if (s < best[r]) { best[r] = s; bi[r] = kg; }
            }
        }
    }

    // ---- cross-thread argmin per row (first-index tie break) ----
    #pragma unroll
    for (int r = 0; r < 4; ++r) {
        redS[(ty * 4 + r) * 16 + tx] = best[r];
        redI[(ty * 4 + r) * 16 + tx] = bi[r];
    }
    __syncthreads();
    if (tid < BM) {
        float b  = redS[tid * 16];
        int   ib = redI[tid * 16];
        #pragma unroll
        for (int t = 1; t < 16; ++t) {
            float s  = redS[tid * 16 + t];
            int   i2 = redI[tid * 16 + t];
            if (s < b || (s == b && i2 < ib)) { b = s; ib = i2; }
        }
        bidx[tid] = ib;
    }
    __syncthreads();

    // ---- update: gather code, straight-through fq, residual, loss ----
    double lacc = 0.0;
    #pragma unroll
    for (int it = 0; it < 16; ++it) {
        int f  = tid + it * NTHREADS;
        int m  = f >> 6;
        int d4 = f & 63;
        size_t off = (size_t)(m0 + m) * DDIM + d4 * 4;
        float4 r4 = *(const float4*)(zin + off);
        float4 c4 = *(const float4*)(cbg + (size_t)bidx[m] * DDIM + d4 * 4);
        float4 fo, rn;
        float4 fprev;
        if (!firstStage) fprev = *(const float4*)(fq + off);

        // exact reference rounding chain per element:
        // t = c - r; st = r + t; fq (+)= st; r_next = r - st; loss += t*t
        {
            float t = c4.x - r4.x; float st = r4.x + t;
            fo.x = firstStage ? st : (fprev.x + st); rn.x = r4.x - st;
            lacc += (double)t * (double)t;
        }
        {
            float t = c4.y - r4.y; float st = r4.y + t;
            fo.y = firstStage ? st : (fprev.y + st); rn.y = r4.y - st;
            lacc += (double)t * (double)t;
        }
        {
            float t = c4.z - r4.z; float st = r4.z + t;
            fo.z = firstStage ? st : (fprev.z + st); rn.z = r4.z - st;
            lacc += (double)t * (double)t;
        }
        {
            float t = c4.w - r4.w; float st = r4.w + t;
            fo.w = firstStage ? st : (fprev.w + st); rn.w = r4.w - st;
            lacc += (double)t * (double)t;
        }
        *(float4*)(fq + off) = fo;
        if (writeR) *(float4*)(rout + off) = rn;
    }

    // warp-reduce loss, one atomic per warp
    #pragma unroll
    for (int o = 16; o; o >>= 1) lacc += __shfl_down_sync(0xffffffffu, lacc, o);
    if ((tid & 31) == 0) atomicAdd(lossp, lacc);
}

// ---------------- finalize: write the two (identical) loss scalars ----------------
__global__ void rvq_finalize_kernel(const double* __restrict__ loss, float* __restrict__ out)
{
    if (blockIdx.x == 0 && threadIdx.x == 0) {
        const double nd = (double)((size_t)NROWS * DDIM);
        float L = 0.f;
        for (int i = 0; i < NCB; ++i) L = L + (float)(loss[i] / nd);  // per-stage mean, summed in fp32 like ref
        out[(size_t)NROWS * DDIM]     = L;  // codebook_losses
        out[(size_t)NROWS * DDIM + 1] = L;  // commitment_losses (numerically identical forward)
    }
}

// ---------------- launch ----------------
extern "C" void kernel_launch(void* const* d_in, const int* in_sizes, int n_in,
                              void* d_out, int out_size)
{
    const float* z  = (const float*)d_in[0];   // [65536, 256]
    const float* cb = (const float*)d_in[1];   // [3, 1024, 256]
    float* out = (float*)d_out;

    float*  res_p  = nullptr;
    float*  c2_p   = nullptr;
    double* loss_p = nullptr;
    cudaGetSymbolAddress((void**)&res_p,  g_res);
    cudaGetSymbolAddress((void**)&c2_p,   g_c2);
    cudaGetSymbolAddress((void**)&loss_p, g_loss);

    cudaFuncSetAttribute(rvq_stage_kernel,
                         cudaFuncAttributeMaxDynamicSharedMemorySize, SMEM_BYTES);

    const int nblk = NROWS / BM;  // 1024

    rvq_init_kernel<<<(NCB * KCB * 32) / NTHREADS, NTHREADS>>>(cb, c2_p, loss_p);

    // stage 0: reads z, writes fq (init) + residual
    rvq_stage_kernel<<<nblk, NTHREADS, SMEM_BYTES>>>(
        z, cb, c2_p, out, res_p, loss_p + 0, /*firstStage=*/1, /*writeR=*/1);
    // stage 1: in-place residual (rows block-exclusive, read-before-write)
    rvq_stage_kernel<<<nblk, NTHREADS, SMEM_BYTES>>>(
        res_p, cb + (size_t)KCB * DDIM, c2_p + KCB, out, res_p, loss_p + 1, 0, 1);
    // stage 2: residual output unused -> skip write
    rvq_stage_kernel<<<nblk, NTHREADS, SMEM_BYTES>>>(
        res_p, cb + (size_t)2 * KCB * DDIM, c2_p + 2 * KCB, out, res_p, loss_p + 2, 0, 0);

    rvq_finalize_kernel<<<1, 32>>>(loss_p, out);
}